// round 1
// baseline (speedup 1.0000x reference)
#include <cuda_runtime.h>

#define N_NODES 100000
#define N_EDGES 1600000
#define D 128
#define ROWS_PER_BLK 64

// Scratch for hn = (features @ W^T + b) * norm  (51.2 MB, static device global)
__device__ float g_hn[(size_t)N_NODES * D];

// ---------------------------------------------------------------------------
// Kernel 1: hn[n,:] = (features[n,:] @ W^T + b) * norm[n]
// Block: 64 rows x 128 cols. 256 threads, each computes 8 rows x 4 cols.
// W (transposed) + A tile fully staged in 96 KB dynamic smem.
// ---------------------------------------------------------------------------
__global__ void __launch_bounds__(256, 2) gemm_norm_kernel(
    const float* __restrict__ A,
    const float* __restrict__ norm,
    const float* __restrict__ W,
    const float* __restrict__ b)
{
    extern __shared__ float smem[];
    float* Ws = smem;              // [128][128], Ws[k*128+j] = W[j][k]
    float* As = smem + D * D;      // [64][128]

    const int tid = threadIdx.x;
    const int tx  = tid & 31;      // lane -> 4 output cols (tx*4..tx*4+3)
    const int ty  = tid >> 5;      // warp -> 8 output rows (ty*8..ty*8+7)
    const int row0 = blockIdx.x * ROWS_PER_BLK;

    // Load W transposed into smem (coalesced gmem read, conflict-free store)
    for (int idx = tid; idx < D * D; idx += 256) {
        int j = idx >> 7, k = idx & 127;
        Ws[k * D + j] = W[idx];
    }
    // Load A tile (64 x 128) as float4, zero-pad tail rows
    for (int idx = tid; idx < ROWS_PER_BLK * (D / 4); idx += 256) {
        int r = idx >> 5;          // 0..63
        int grow = row0 + r;
        float4 v = make_float4(0.f, 0.f, 0.f, 0.f);
        if (grow < N_NODES)
            v = reinterpret_cast<const float4*>(A)[(size_t)grow * 32 + (idx & 31)];
        reinterpret_cast<float4*>(As)[idx] = v;
    }
    __syncthreads();

    float acc[8][4];
#pragma unroll
    for (int r = 0; r < 8; r++)
#pragma unroll
        for (int c = 0; c < 4; c++) acc[r][c] = 0.f;

#pragma unroll 8
    for (int k = 0; k < D; k++) {
        // w = W^T[k][tx*4 .. tx*4+3]  (lanes span all banks, conflict-free)
        float4 w = reinterpret_cast<const float4*>(Ws + k * D)[tx];
#pragma unroll
        for (int r = 0; r < 8; r++) {
            float a = As[(ty * 8 + r) * D + k];   // broadcast within warp
            acc[r][0] += a * w.x;
            acc[r][1] += a * w.y;
            acc[r][2] += a * w.z;
            acc[r][3] += a * w.w;
        }
    }

    float4 bb = reinterpret_cast<const float4*>(b)[tx];
#pragma unroll
    for (int r = 0; r < 8; r++) {
        int grow = row0 + ty * 8 + r;
        if (grow < N_NODES) {
            float nr = norm[grow];
            float4 o;
            o.x = (acc[r][0] + bb.x) * nr;
            o.y = (acc[r][1] + bb.y) * nr;
            o.z = (acc[r][2] + bb.z) * nr;
            o.w = (acc[r][3] + bb.w) * nr;
            reinterpret_cast<float4*>(g_hn)[(size_t)grow * 32 + tx] = o;
        }
    }
}

// ---------------------------------------------------------------------------
// Kernel 2: edge scatter. One warp per edge; each lane moves one float4
// (512 B contiguous per edge on both gather and scatter side).
// hn and agg both fit in L2 -> expect L2-resident traffic.
// ---------------------------------------------------------------------------
__global__ void __launch_bounds__(256) scatter_kernel(
    const int* __restrict__ src,
    const int* __restrict__ dst,
    float* __restrict__ agg)
{
    unsigned t = blockIdx.x * 256u + threadIdx.x;
    unsigned e = t >> 5;
    if (e >= N_EDGES) return;
    int lane = t & 31;
    int s = __ldg(&src[e]);
    int d = __ldg(&dst[e]);

    float4 v = reinterpret_cast<const float4*>(g_hn)[(size_t)s * 32 + lane];
    float4* op = reinterpret_cast<float4*>(agg) + (size_t)d * 32 + lane;
    asm volatile("red.global.add.v4.f32 [%0], {%1, %2, %3, %4};"
                 :: "l"(op), "f"(v.x), "f"(v.y), "f"(v.z), "f"(v.w)
                 : "memory");
}

// ---------------------------------------------------------------------------
// Kernel 3: out = relu(agg * norm[node])  (in place on d_out)
// ---------------------------------------------------------------------------
__global__ void __launch_bounds__(256) finalize_kernel(
    float* __restrict__ out, const float* __restrict__ norm)
{
    unsigned i = blockIdx.x * 256u + threadIdx.x;   // float4 index
    if (i >= (unsigned)N_NODES * 32u) return;
    float nr = norm[i >> 5];
    float4* p = reinterpret_cast<float4*>(out) + i;
    float4 v = *p;
    v.x = fmaxf(v.x * nr, 0.f);
    v.y = fmaxf(v.y * nr, 0.f);
    v.z = fmaxf(v.z * nr, 0.f);
    v.w = fmaxf(v.w * nr, 0.f);
    *p = v;
}

// ---------------------------------------------------------------------------
extern "C" void kernel_launch(void* const* d_in, const int* in_sizes, int n_in,
                              void* d_out, int out_size)
{
    const float* features = (const float*)d_in[0];
    const float* norm     = (const float*)d_in[1];
    const float* W        = (const float*)d_in[2];
    const float* b        = (const float*)d_in[3];
    const int*   src      = (const int*)d_in[4];
    const int*   dst      = (const int*)d_in[5];
    float* out = (float*)d_out;

    const int smem_bytes = (D * D + ROWS_PER_BLK * D) * sizeof(float); // 96 KB
    cudaFuncSetAttribute(gemm_norm_kernel,
                         cudaFuncAttributeMaxDynamicSharedMemorySize, smem_bytes);

    // Zero the accumulator (d_out) while GEMM runs logically before scatter.
    cudaMemsetAsync(out, 0, (size_t)N_NODES * D * sizeof(float));

    int gemm_blocks = (N_NODES + ROWS_PER_BLK - 1) / ROWS_PER_BLK; // 1563
    gemm_norm_kernel<<<gemm_blocks, 256, smem_bytes>>>(features, norm, W, b);

    unsigned scatter_blocks = ((unsigned)N_EDGES * 32u + 255u) / 256u; // 200000
    scatter_kernel<<<scatter_blocks, 256>>>(src, dst, out);

    unsigned fin_blocks = ((unsigned)N_NODES * 32u + 255u) / 256u; // 12500
    finalize_kernel<<<fin_blocks, 256>>>(out, norm);
}

// round 2
// speedup vs baseline: 1.0150x; 1.0150x over previous
#include <cuda_runtime.h>

#define N_NODES 100000
#define N_EDGES 1600000
#define D 128
#define ROWS_PER_BLK 64

// Scratch for hn = (features @ W^T + b) * norm  (51.2 MB, static device global)
__device__ float g_hn[(size_t)N_NODES * D];

// ---------------------------------------------------------------------------
// Kernel 1: hn[n,:] = (features[n,:] @ W^T + b) * norm[n]
// Block: 64 rows x 128 cols. 256 threads, each computes 8 rows x 4 cols.
// W (transposed) + A tile fully staged in 96 KB dynamic smem.
// ---------------------------------------------------------------------------
__global__ void __launch_bounds__(256, 2) gemm_norm_kernel(
    const float* __restrict__ A,
    const float* __restrict__ norm,
    const float* __restrict__ W,
    const float* __restrict__ b)
{
    extern __shared__ float smem[];
    float* Ws = smem;              // [128][128], Ws[k*128+j] = W[j][k]
    float* As = smem + D * D;      // [64][128]

    const int tid = threadIdx.x;
    const int tx  = tid & 31;      // lane -> 4 output cols (tx*4..tx*4+3)
    const int ty  = tid >> 5;      // warp -> 8 output rows (ty*8..ty*8+7)
    const int row0 = blockIdx.x * ROWS_PER_BLK;

    // Load W transposed into smem (coalesced gmem read, conflict-free store)
    for (int idx = tid; idx < D * D; idx += 256) {
        int j = idx >> 7, k = idx & 127;
        Ws[k * D + j] = W[idx];
    }
    // Load A tile (64 x 128) as float4, zero-pad tail rows
    for (int idx = tid; idx < ROWS_PER_BLK * (D / 4); idx += 256) {
        int r = idx >> 5;          // 0..63
        int grow = row0 + r;
        float4 v = make_float4(0.f, 0.f, 0.f, 0.f);
        if (grow < N_NODES)
            v = reinterpret_cast<const float4*>(A)[(size_t)grow * 32 + (idx & 31)];
        reinterpret_cast<float4*>(As)[idx] = v;
    }
    __syncthreads();

    float acc[8][4];
#pragma unroll
    for (int r = 0; r < 8; r++)
#pragma unroll
        for (int c = 0; c < 4; c++) acc[r][c] = 0.f;

#pragma unroll 8
    for (int k = 0; k < D; k++) {
        // w = W^T[k][tx*4 .. tx*4+3]  (lanes span all banks, conflict-free)
        float4 w = reinterpret_cast<const float4*>(Ws + k * D)[tx];
#pragma unroll
        for (int r = 0; r < 8; r++) {
            float a = As[(ty * 8 + r) * D + k];   // broadcast within warp
            acc[r][0] += a * w.x;
            acc[r][1] += a * w.y;
            acc[r][2] += a * w.z;
            acc[r][3] += a * w.w;
        }
    }

    float4 bb = reinterpret_cast<const float4*>(b)[tx];
#pragma unroll
    for (int r = 0; r < 8; r++) {
        int grow = row0 + ty * 8 + r;
        if (grow < N_NODES) {
            float nr = norm[grow];
            float4 o;
            o.x = (acc[r][0] + bb.x) * nr;
            o.y = (acc[r][1] + bb.y) * nr;
            o.z = (acc[r][2] + bb.z) * nr;
            o.w = (acc[r][3] + bb.w) * nr;
            reinterpret_cast<float4*>(g_hn)[(size_t)grow * 32 + tx] = o;
        }
    }
}

// ---------------------------------------------------------------------------
// Kernel 2: edge scatter. One warp per edge; each lane moves one float4
// (512 B contiguous per edge on both gather and scatter side).
// hn and agg both fit in L2 -> expect L2-resident traffic.
// ---------------------------------------------------------------------------
__global__ void __launch_bounds__(256) scatter_kernel(
    const int* __restrict__ src,
    const int* __restrict__ dst,
    float* __restrict__ agg)
{
    unsigned t = blockIdx.x * 256u + threadIdx.x;
    unsigned e = t >> 5;
    if (e >= N_EDGES) return;
    int lane = t & 31;
    int s = __ldg(&src[e]);
    int d = __ldg(&dst[e]);

    float4 v = reinterpret_cast<const float4*>(g_hn)[(size_t)s * 32 + lane];
    float4* op = reinterpret_cast<float4*>(agg) + (size_t)d * 32 + lane;
    asm volatile("red.global.add.v4.f32 [%0], {%1, %2, %3, %4};"
                 :: "l"(op), "f"(v.x), "f"(v.y), "f"(v.z), "f"(v.w)
                 : "memory");
}

// ---------------------------------------------------------------------------
// Kernel 3: out = relu(agg * norm[node])  (in place on d_out)
// ---------------------------------------------------------------------------
__global__ void __launch_bounds__(256) finalize_kernel(
    float* __restrict__ out, const float* __restrict__ norm)
{
    unsigned i = blockIdx.x * 256u + threadIdx.x;   // float4 index
    if (i >= (unsigned)N_NODES * 32u) return;
    float nr = norm[i >> 5];
    float4* p = reinterpret_cast<float4*>(out) + i;
    float4 v = *p;
    v.x = fmaxf(v.x * nr, 0.f);
    v.y = fmaxf(v.y * nr, 0.f);
    v.z = fmaxf(v.z * nr, 0.f);
    v.w = fmaxf(v.w * nr, 0.f);
    *p = v;
}

// ---------------------------------------------------------------------------
extern "C" void kernel_launch(void* const* d_in, const int* in_sizes, int n_in,
                              void* d_out, int out_size)
{
    const float* features = (const float*)d_in[0];
    const float* norm     = (const float*)d_in[1];
    const float* W        = (const float*)d_in[2];
    const float* b        = (const float*)d_in[3];
    const int*   src      = (const int*)d_in[4];
    const int*   dst      = (const int*)d_in[5];
    float* out = (float*)d_out;

    const int smem_bytes = (D * D + ROWS_PER_BLK * D) * sizeof(float); // 96 KB
    cudaFuncSetAttribute(gemm_norm_kernel,
                         cudaFuncAttributeMaxDynamicSharedMemorySize, smem_bytes);

    // Zero the accumulator (d_out) while GEMM runs logically before scatter.
    cudaMemsetAsync(out, 0, (size_t)N_NODES * D * sizeof(float));

    int gemm_blocks = (N_NODES + ROWS_PER_BLK - 1) / ROWS_PER_BLK; // 1563
    gemm_norm_kernel<<<gemm_blocks, 256, smem_bytes>>>(features, norm, W, b);

    unsigned scatter_blocks = ((unsigned)N_EDGES * 32u + 255u) / 256u; // 200000
    scatter_kernel<<<scatter_blocks, 256>>>(src, dst, out);

    unsigned fin_blocks = ((unsigned)N_NODES * 32u + 255u) / 256u; // 12500
    finalize_kernel<<<fin_blocks, 256>>>(out, norm);
}